// round 1
// baseline (speedup 1.0000x reference)
#include <cuda_runtime.h>
#include <cstdint>

#define HEAD_DIM 64
#define EMB_DIM 1024
#define BATCH 4
#define SEQ 4096
#define MTOT (BATCH*SEQ)

// Scratch for Q, K, V projections (4 MB each)
__device__ float g_Q[(size_t)MTOT * HEAD_DIM];
__device__ float g_K[(size_t)MTOT * HEAD_DIM];
__device__ float g_V[(size_t)MTOT * HEAD_DIM];

__device__ __forceinline__ float f2tf(float f) {
    uint32_t r;
    asm("cvt.rna.tf32.f32 %0, %1;" : "=r"(r) : "f"(f));
    return __uint_as_float(r);
}
__device__ __forceinline__ uint32_t fu(float f) { return __float_as_uint(f); }

__device__ __forceinline__ void mma8(float* c, const uint32_t* a, uint32_t b0, uint32_t b1) {
    asm volatile(
        "mma.sync.aligned.m16n8k8.row.col.f32.tf32.tf32.f32 "
        "{%0,%1,%2,%3}, {%4,%5,%6,%7}, {%8,%9}, {%0,%1,%2,%3};"
        : "+f"(c[0]), "+f"(c[1]), "+f"(c[2]), "+f"(c[3])
        : "r"(a[0]), "r"(a[1]), "r"(a[2]), "r"(a[3]), "r"(b0), "r"(b1));
}

// ---------------------------------------------------------------------------
// Kernel 1: QKV projection.  C[M=16384, N=64] = x[M, 1024] @ W[1024, 64]
// grid (M/64, 3), block 128.  BM=64, BN=64, BK=16.
// smem pads: xs row stride 20 (bank map 20r+c distinct mod 32 for frag loads),
//            ws row stride 68 (4k+n distinct mod 32).
// ---------------------------------------------------------------------------
__global__ __launch_bounds__(128) void qkv_proj_kernel(
    const float* __restrict__ x, const float* __restrict__ Wq,
    const float* __restrict__ Wk, const float* __restrict__ Wv)
{
    __shared__ float xs[64 * 20];
    __shared__ float ws[16 * 68];
    const int t = threadIdx.x;
    const int warp = t >> 5, lane = t & 31;
    const float* W;
    float* Out;
    if (blockIdx.y == 0)      { W = Wq; Out = g_Q; }
    else if (blockIdx.y == 1) { W = Wk; Out = g_K; }
    else                      { W = Wv; Out = g_V; }
    const int m0 = blockIdx.x * 64;
    const int rl = warp * 16 + (lane >> 2);   // row 0..63 within tile (low half)
    const int cq = lane & 3;

    float acc[8][4];
#pragma unroll
    for (int n = 0; n < 8; n++) { acc[n][0] = acc[n][1] = acc[n][2] = acc[n][3] = 0.f; }

    for (int kc = 0; kc < EMB_DIM / 16; kc++) {
        // load x tile [64 x 16]
#pragma unroll
        for (int i = 0; i < 2; i++) {
            int f = i * 128 + t;
            int row = f >> 2, c4 = f & 3;
            const float4 v = *reinterpret_cast<const float4*>(
                x + (size_t)(m0 + row) * EMB_DIM + kc * 16 + c4 * 4);
            float* dst = &xs[row * 20 + c4 * 4];
            dst[0] = f2tf(v.x); dst[1] = f2tf(v.y); dst[2] = f2tf(v.z); dst[3] = f2tf(v.w);
        }
        // load W tile [16 x 64]
#pragma unroll
        for (int i = 0; i < 2; i++) {
            int f = i * 128 + t;
            int row = f >> 4, c4 = f & 15;
            const float4 v = *reinterpret_cast<const float4*>(
                W + (size_t)(kc * 16 + row) * HEAD_DIM + c4 * 4);
            float* dst = &ws[row * 68 + c4 * 4];
            dst[0] = f2tf(v.x); dst[1] = f2tf(v.y); dst[2] = f2tf(v.z); dst[3] = f2tf(v.w);
        }
        __syncthreads();

        uint32_t a[2][4];
#pragma unroll
        for (int kk = 0; kk < 2; kk++) {
            a[kk][0] = fu(xs[rl * 20       + kk * 8 + cq]);
            a[kk][1] = fu(xs[(rl + 8) * 20 + kk * 8 + cq]);
            a[kk][2] = fu(xs[rl * 20       + kk * 8 + cq + 4]);
            a[kk][3] = fu(xs[(rl + 8) * 20 + kk * 8 + cq + 4]);
        }
#pragma unroll
        for (int n = 0; n < 8; n++) {
#pragma unroll
            for (int kk = 0; kk < 2; kk++) {
                uint32_t b0 = fu(ws[(kk * 8 + cq) * 68     + n * 8 + (lane >> 2)]);
                uint32_t b1 = fu(ws[(kk * 8 + 4 + cq) * 68 + n * 8 + (lane >> 2)]);
                mma8(acc[n], a[kk], b0, b1);
            }
        }
        __syncthreads();
    }

#pragma unroll
    for (int n = 0; n < 8; n++) {
        int c = n * 8 + 2 * cq;
        *reinterpret_cast<float2*>(Out + (size_t)(m0 + rl) * HEAD_DIM + c) =
            make_float2(acc[n][0], acc[n][1]);
        *reinterpret_cast<float2*>(Out + (size_t)(m0 + rl + 8) * HEAD_DIM + c) =
            make_float2(acc[n][2], acc[n][3]);
    }
}

// ---------------------------------------------------------------------------
// Kernel 2: causal flash attention, 64x64 Q tile per block, grid (64, 4).
// 4 warps x 16 q-rows. Online softmax (FA2). P stays in registers via
// quad shuffles (S accumulator layout -> tf32 A-fragment layout).
// ---------------------------------------------------------------------------
__global__ __launch_bounds__(128) void attn_kernel(float* __restrict__ out)
{
    extern __shared__ float smem[];
    float* qs = smem;                  // [64][68]
    float* ks = smem + 64 * 68;        // [64][68]
    float* vs = smem + 2 * 64 * 68;    // [64][68]

    const int t = threadIdx.x, warp = t >> 5, lane = t & 31;
    const int b = blockIdx.y, qi = blockIdx.x;
    const int q0 = qi * 64;
    const int rl = warp * 16 + (lane >> 2);  // q-row within tile (low half)
    const int cq = lane & 3;

    // Load Q tile, pre-scaled by 1/sqrt(64)
    const float* Qg = g_Q + ((size_t)b * SEQ + q0) * HEAD_DIM;
#pragma unroll
    for (int i = 0; i < 8; i++) {
        int f = i * 128 + t;
        int row = f >> 4, c4 = f & 15;
        const float4 v = *reinterpret_cast<const float4*>(Qg + row * HEAD_DIM + c4 * 4);
        float* dst = &qs[row * 68 + c4 * 4];
        dst[0] = f2tf(v.x * 0.125f); dst[1] = f2tf(v.y * 0.125f);
        dst[2] = f2tf(v.z * 0.125f); dst[3] = f2tf(v.w * 0.125f);
    }
    __syncthreads();

    // Q A-fragments held in registers for the whole kernel
    uint32_t aq[8][4];
#pragma unroll
    for (int kk = 0; kk < 8; kk++) {
        aq[kk][0] = fu(qs[rl * 68       + kk * 8 + cq]);
        aq[kk][1] = fu(qs[(rl + 8) * 68 + kk * 8 + cq]);
        aq[kk][2] = fu(qs[rl * 68       + kk * 8 + cq + 4]);
        aq[kk][3] = fu(qs[(rl + 8) * 68 + kk * 8 + cq + 4]);
    }

    float m0 = -1e30f, m1 = -1e30f, l0 = 0.f, l1 = 0.f;
    float o[8][4];
#pragma unroll
    for (int n = 0; n < 8; n++) { o[n][0] = o[n][1] = o[n][2] = o[n][3] = 0.f; }

    for (int j = 0; j <= qi; j++) {
        const float* Kg = g_K + ((size_t)b * SEQ + j * 64) * HEAD_DIM;
        const float* Vg = g_V + ((size_t)b * SEQ + j * 64) * HEAD_DIM;
        __syncthreads();   // previous iteration's readers done before overwrite
#pragma unroll
        for (int i = 0; i < 8; i++) {
            int f = i * 128 + t;
            int row = f >> 4, c4 = f & 15;
            const float4 kv = *reinterpret_cast<const float4*>(Kg + row * HEAD_DIM + c4 * 4);
            float* kd = &ks[row * 68 + c4 * 4];
            kd[0] = f2tf(kv.x); kd[1] = f2tf(kv.y); kd[2] = f2tf(kv.z); kd[3] = f2tf(kv.w);
            const float4 vv = *reinterpret_cast<const float4*>(Vg + row * HEAD_DIM + c4 * 4);
            float* vd = &vs[row * 68 + c4 * 4];
            vd[0] = f2tf(vv.x); vd[1] = f2tf(vv.y); vd[2] = f2tf(vv.z); vd[3] = f2tf(vv.w);
        }
        __syncthreads();

        // S = Q @ K^T   [16 q-rows x 64 keys per warp]
        float s[8][4];
#pragma unroll
        for (int n = 0; n < 8; n++) { s[n][0] = s[n][1] = s[n][2] = s[n][3] = 0.f; }
#pragma unroll
        for (int n = 0; n < 8; n++) {
#pragma unroll
            for (int kk = 0; kk < 8; kk++) {
                uint32_t b0 = fu(ks[(n * 8 + (lane >> 2)) * 68 + kk * 8 + cq]);
                uint32_t b1 = fu(ks[(n * 8 + (lane >> 2)) * 68 + kk * 8 + cq + 4]);
                mma8(s[n], aq[kk], b0, b1);
            }
        }

        if (j == qi) {   // causal mask on diagonal tile (key > query)
#pragma unroll
            for (int n = 0; n < 8; n++) {
                int c0 = n * 8 + 2 * cq;
                if (c0     > rl)     s[n][0] = -1e30f;
                if (c0 + 1 > rl)     s[n][1] = -1e30f;
                if (c0     > rl + 8) s[n][2] = -1e30f;
                if (c0 + 1 > rl + 8) s[n][3] = -1e30f;
            }
        }

        // online softmax (rows rl and rl+8)
        float nm0 = m0, nm1 = m1;
#pragma unroll
        for (int n = 0; n < 8; n++) {
            nm0 = fmaxf(nm0, fmaxf(s[n][0], s[n][1]));
            nm1 = fmaxf(nm1, fmaxf(s[n][2], s[n][3]));
        }
        nm0 = fmaxf(nm0, __shfl_xor_sync(0xffffffffu, nm0, 1));
        nm0 = fmaxf(nm0, __shfl_xor_sync(0xffffffffu, nm0, 2));
        nm1 = fmaxf(nm1, __shfl_xor_sync(0xffffffffu, nm1, 1));
        nm1 = fmaxf(nm1, __shfl_xor_sync(0xffffffffu, nm1, 2));
        float sc0 = __expf(m0 - nm0), sc1 = __expf(m1 - nm1);
        m0 = nm0; m1 = nm1;

        float sum0 = 0.f, sum1 = 0.f;
#pragma unroll
        for (int n = 0; n < 8; n++) {
            float p0 = __expf(s[n][0] - nm0);
            float p1 = __expf(s[n][1] - nm0);
            float p2 = __expf(s[n][2] - nm1);
            float p3 = __expf(s[n][3] - nm1);
            sum0 += p0 + p1; sum1 += p2 + p3;
            s[n][0] = f2tf(p0); s[n][1] = f2tf(p1);
            s[n][2] = f2tf(p2); s[n][3] = f2tf(p3);
        }
        sum0 += __shfl_xor_sync(0xffffffffu, sum0, 1);
        sum0 += __shfl_xor_sync(0xffffffffu, sum0, 2);
        sum1 += __shfl_xor_sync(0xffffffffu, sum1, 1);
        sum1 += __shfl_xor_sync(0xffffffffu, sum1, 2);
        l0 = l0 * sc0 + sum0;
        l1 = l1 * sc1 + sum1;
#pragma unroll
        for (int n = 0; n < 8; n++) {
            o[n][0] *= sc0; o[n][1] *= sc0; o[n][2] *= sc1; o[n][3] *= sc1;
        }

        // O += P @ V.  Rearrange P accum layout -> A fragment via quad shuffles:
        // lane (quad pos q) needs cols {q, q+4}; accum lane s holds cols {2s, 2s+1}.
        const int src0 = (lane & 28) | (cq >> 1);
        const int src1 = src0 + 2;
        const bool odd = (cq & 1);
#pragma unroll
        for (int tt = 0; tt < 8; tt++) {
            float v00 = __shfl_sync(0xffffffffu, s[tt][0], src0);
            float v01 = __shfl_sync(0xffffffffu, s[tt][1], src0);
            float w00 = __shfl_sync(0xffffffffu, s[tt][2], src0);
            float w01 = __shfl_sync(0xffffffffu, s[tt][3], src0);
            float v10 = __shfl_sync(0xffffffffu, s[tt][0], src1);
            float v11 = __shfl_sync(0xffffffffu, s[tt][1], src1);
            float w10 = __shfl_sync(0xffffffffu, s[tt][2], src1);
            float w11 = __shfl_sync(0xffffffffu, s[tt][3], src1);
            uint32_t a[4];
            a[0] = fu(odd ? v01 : v00);   // P[rl  ][8tt+cq]
            a[1] = fu(odd ? w01 : w00);   // P[rl+8][8tt+cq]
            a[2] = fu(odd ? v11 : v10);   // P[rl  ][8tt+cq+4]
            a[3] = fu(odd ? w11 : w10);   // P[rl+8][8tt+cq+4]
#pragma unroll
            for (int n = 0; n < 8; n++) {
                uint32_t b0 = fu(vs[(tt * 8 + cq) * 68     + n * 8 + (lane >> 2)]);
                uint32_t b1 = fu(vs[(tt * 8 + cq + 4) * 68 + n * 8 + (lane >> 2)]);
                mma8(o[n], a, b0, b1);
            }
        }
    }

    const float i0 = 1.f / l0, i1 = 1.f / l1;
    float* Og = out + ((size_t)b * SEQ + q0) * HEAD_DIM;
#pragma unroll
    for (int n = 0; n < 8; n++) {
        int c = n * 8 + 2 * cq;
        *reinterpret_cast<float2*>(Og + rl * HEAD_DIM + c) =
            make_float2(o[n][0] * i0, o[n][1] * i0);
        *reinterpret_cast<float2*>(Og + (rl + 8) * HEAD_DIM + c) =
            make_float2(o[n][2] * i1, o[n][3] * i1);
    }
}

extern "C" void kernel_launch(void* const* d_in, const int* in_sizes, int n_in,
                              void* d_out, int out_size) {
    const float* x  = (const float*)d_in[0];
    const float* Wq = (const float*)d_in[1];
    const float* Wk = (const float*)d_in[2];
    const float* Wv = (const float*)d_in[3];
    float* out = (float*)d_out;

    qkv_proj_kernel<<<dim3(MTOT / 64, 3), 128>>>(x, Wq, Wk, Wv);

    const int attn_smem = 3 * 64 * 68 * sizeof(float);   // 52224 B
    cudaFuncSetAttribute(attn_kernel, cudaFuncAttributeMaxDynamicSharedMemorySize, attn_smem);
    attn_kernel<<<dim3(SEQ / 64, BATCH), 128, attn_smem>>>(out);
}